// round 2
// baseline (speedup 1.0000x reference)
#include <cuda_runtime.h>
#include <math.h>

// Problem constants (B=4096, I=H=1024, 4H=4096)
#define MB 4096
#define KK 1024
#define NN 4096
#define HH 1024

// ---------------- scratch (allocation-free: device globals) ----------------
__device__ float g_pre_i2h[(size_t)MB * NN];  // input @ w_i2h   (64 MB)
__device__ float g_pre_h2h[(size_t)MB * NN];  // h_prev @ w_h2h  (64 MB)

// ---------------- GEMM: C = A[M,K] @ B[K,N], all row-major ----------------
#define BM 128
#define BN 128
#define BK 8
#define TM 8
#define TN 8

__global__ __launch_bounds__(256, 2)
void sgemm_dual(const float* __restrict__ A0, const float* __restrict__ B0,
                const float* __restrict__ A1, const float* __restrict__ B1)
{
    const float* A = (blockIdx.z == 0) ? A0 : A1;
    const float* B = (blockIdx.z == 0) ? B0 : B1;
    float* C = (blockIdx.z == 0) ? g_pre_i2h : g_pre_h2h;

    __shared__ float As[BK][BM];
    __shared__ float Bs[BK][BN];

    const int tid = threadIdx.x;            // 0..255
    const int tx = tid & 15;                // 16 x 16 thread grid
    const int ty = tid >> 4;

    const float* Ablk = A + (size_t)blockIdx.y * BM * KK;
    const float* Bblk = B + (size_t)blockIdx.x * BN;

    // A tile loads: 128 rows x 8 cols -> 256 threads x 1 float4
    const int aRow = tid >> 1;
    const int aCol = (tid & 1) * 4;
    // B tile loads: 8 rows x 128 cols -> 256 threads x 1 float4
    const int bRow = tid >> 5;
    const int bCol = (tid & 31) * 4;

    float acc[TM][TN];
    #pragma unroll
    for (int i = 0; i < TM; i++)
        #pragma unroll
        for (int j = 0; j < TN; j++)
            acc[i][j] = 0.0f;

    for (int k0 = 0; k0 < KK; k0 += BK) {
        float4 av = *reinterpret_cast<const float4*>(Ablk + (size_t)aRow * KK + k0 + aCol);
        As[aCol + 0][aRow] = av.x;
        As[aCol + 1][aRow] = av.y;
        As[aCol + 2][aRow] = av.z;
        As[aCol + 3][aRow] = av.w;
        float4 bv = *reinterpret_cast<const float4*>(Bblk + (size_t)(k0 + bRow) * NN + bCol);
        *reinterpret_cast<float4*>(&Bs[bRow][bCol]) = bv;
        __syncthreads();

        #pragma unroll
        for (int k = 0; k < BK; k++) {
            float a[TM], b[TN];
            #pragma unroll
            for (int i = 0; i < TM; i++) a[i] = As[k][ty * TM + i];
            #pragma unroll
            for (int j = 0; j < TN; j++) b[j] = Bs[k][tx * TN + j];
            #pragma unroll
            for (int i = 0; i < TM; i++)
                #pragma unroll
                for (int j = 0; j < TN; j++)
                    acc[i][j] = fmaf(a[i], b[j], acc[i][j]);
        }
        __syncthreads();
    }

    float* Cblk = C + (size_t)(blockIdx.y * BM) * NN + blockIdx.x * BN;
    #pragma unroll
    for (int i = 0; i < TM; i++) {
        #pragma unroll
        for (int j = 0; j < TN; j += 4) {
            float4 v = make_float4(acc[i][j], acc[i][j + 1], acc[i][j + 2], acc[i][j + 3]);
            *reinterpret_cast<float4*>(Cblk + (size_t)(ty * TM + i) * NN + tx * TN + j) = v;
        }
    }
}

// ---------------- epilogue: LN + gates + LN + outputs ----------------
#define EPS 1e-6f

__device__ __forceinline__ float sigm(float x) { return 1.0f / (1.0f + expf(-x)); }

// 256-thread block reduction of (sum, sumsq). Result broadcast to all threads.
__device__ void block_reduce2(float& s, float& q)
{
    __shared__ float rs[8], rq[8];
    __shared__ float bs, bq;
    #pragma unroll
    for (int o = 16; o > 0; o >>= 1) {
        s += __shfl_down_sync(0xffffffffu, s, o);
        q += __shfl_down_sync(0xffffffffu, q, o);
    }
    const int w = threadIdx.x >> 5, l = threadIdx.x & 31;
    __syncthreads();                 // protect rs/rq reuse across calls
    if (l == 0) { rs[w] = s; rq[w] = q; }
    __syncthreads();
    if (threadIdx.x == 0) {
        float a = 0.0f, b = 0.0f;
        #pragma unroll
        for (int i = 0; i < 8; i++) { a += rs[i]; b += rq[i]; }
        bs = a; bq = b;
    }
    __syncthreads();
    s = bs; q = bq;
}

__global__ __launch_bounds__(256)
void lstm_epilogue(const float* __restrict__ c_prev,
                   const float* __restrict__ b_i2h, const float* __restrict__ b_h2h,
                   const float* __restrict__ g_i2h, const float* __restrict__ be_i2h,
                   const float* __restrict__ g_h2h, const float* __restrict__ be_h2h,
                   const float* __restrict__ g_c,   const float* __restrict__ be_c,
                   float* __restrict__ out)
{
    __shared__ float sh_g[NN];   // hi pre-act, later gates (hi_n + hh_n)
    __shared__ float sh_h[NN];   // hh pre-act, later [cpre | o]

    const int r = blockIdx.x;
    const int tid = threadIdx.x;
    const float* hi = g_pre_i2h + (size_t)r * NN;
    const float* hh = g_pre_h2h + (size_t)r * NN;

    // --- LN stats for i2h row ---
    float s = 0.0f, q = 0.0f;
    for (int j = tid; j < NN; j += 256) {
        float v = hi[j] + b_i2h[j];
        sh_g[j] = v;
        s += v; q += v * v;
    }
    block_reduce2(s, q);
    const float m1 = s / (float)NN;
    const float v1 = (q - s * s / (float)NN) / (float)(NN - 1);
    const float inv1 = 1.0f / (sqrtf(v1) + EPS);

    // --- LN stats for h2h row ---
    s = 0.0f; q = 0.0f;
    for (int j = tid; j < NN; j += 256) {
        float v = hh[j] + b_h2h[j];
        sh_h[j] = v;
        s += v; q += v * v;
    }
    block_reduce2(s, q);
    const float m2 = s / (float)NN;
    const float v2 = (q - s * s / (float)NN) / (float)(NN - 1);
    const float inv2 = 1.0f / (sqrtf(v2) + EPS);

    // --- normalized sum -> gates ---
    for (int j = tid; j < NN; j += 256) {
        float a = g_i2h[j] * ((sh_g[j] - m1) * inv1) + be_i2h[j];
        float b = g_h2h[j] * ((sh_h[j] - m2) * inv2) + be_h2h[j];
        sh_g[j] = a + b;
    }
    __syncthreads();

    // --- cell pre-activation ---
    s = 0.0f; q = 0.0f;
    for (int k = tid; k < HH; k += 256) {
        float ig = sh_g[k];
        float fg = sh_g[HH + k];
        float ug = sh_g[2 * HH + k];
        float og = sh_g[3 * HH + k];
        float cp = c_prev[(size_t)r * HH + k] * sigm(fg + 1.0f) + tanhf(ug) * sigm(ig);
        sh_h[k] = cp;
        sh_h[HH + k] = og;
        s += cp; q += cp * cp;
    }
    block_reduce2(s, q);
    const float m3 = s / (float)HH;
    const float v3 = (q - s * s / (float)HH) / (float)(HH - 1);
    const float inv3 = 1.0f / (sqrtf(v3) + EPS);

    // --- c = LN(cpre), h = sigmoid(o) * tanh(c) ---
    float* out_h = out;
    float* out_c = out + (size_t)MB * HH;
    for (int k = tid; k < HH; k += 256) {
        float c = g_c[k] * ((sh_h[k] - m3) * inv3) + be_c[k];
        float h = sigm(sh_h[HH + k]) * tanhf(c);
        out_h[(size_t)r * HH + k] = h;
        out_c[(size_t)r * HH + k] = c;
    }
}

// ---------------- launch ----------------
extern "C" void kernel_launch(void* const* d_in, const int* in_sizes, int n_in,
                              void* d_out, int out_size)
{
    const float* input  = (const float*)d_in[0];
    const float* h_prev = (const float*)d_in[1];
    const float* c_prev = (const float*)d_in[2];
    const float* w_i2h  = (const float*)d_in[3];
    const float* b_i2h  = (const float*)d_in[4];
    const float* w_h2h  = (const float*)d_in[5];
    const float* b_h2h  = (const float*)d_in[6];
    const float* g_i2h  = (const float*)d_in[7];
    const float* be_i2h = (const float*)d_in[8];
    const float* g_h2h  = (const float*)d_in[9];
    const float* be_h2h = (const float*)d_in[10];
    const float* g_c    = (const float*)d_in[11];
    const float* be_c   = (const float*)d_in[12];
    float* out = (float*)d_out;

    dim3 gemm_grid(NN / BN, MB / BM, 2);
    sgemm_dual<<<gemm_grid, 256>>>(input, w_i2h, h_prev, w_h2h);

    lstm_epilogue<<<MB, 256>>>(c_prev, b_i2h, b_h2h, g_i2h, be_i2h,
                               g_h2h, be_h2h, g_c, be_c, out);
}

// round 5
// speedup vs baseline: 2.3134x; 2.3134x over previous
#include <cuda_runtime.h>
#include <cuda_bf16.h>
#include <math.h>
#include <stdint.h>

// Problem constants (B=4096, I=H=1024, 4H=4096)
#define MB 4096
#define KK 1024
#define NN 4096
#define HH 1024
#define MTOT 8192              // input rows stacked on h_prev rows
#define KTOT 3072              // 3 * KK  (split-bf16 segments)

// ---------------- scratch (allocation-free: device globals) ----------------
__device__ __align__(1024) __nv_bfloat16 g_Abig[(size_t)MTOT * KTOT];      // 48 MB
__device__ __align__(1024) __nv_bfloat16 g_Bbig[2][(size_t)NN * KTOT];     // 48 MB
__device__ float g_pre_i2h[(size_t)MB * NN];                               // 64 MB
__device__ float g_pre_h2h[(size_t)MB * NN];                               // 64 MB

// ========================= PTX helpers =========================
__device__ __forceinline__ uint32_t smem_u32(const void* p) {
    uint32_t a;
    asm("{ .reg .u64 t; cvta.to.shared.u64 t, %1; cvt.u32.u64 %0, t; }" : "=r"(a) : "l"(p));
    return a;
}
__device__ __forceinline__ void cp_async16(uint32_t saddr, const void* gaddr) {
    asm volatile("cp.async.cg.shared.global [%0], [%1], 16;" :: "r"(saddr), "l"(gaddr));
}
#define CP_COMMIT() asm volatile("cp.async.commit_group;" ::: "memory")
#define CP_WAIT_GROUP(n) asm volatile("cp.async.wait_group %0;" :: "n"(n) : "memory")

__device__ __forceinline__ void ldsm_x4(uint32_t& r0, uint32_t& r1, uint32_t& r2, uint32_t& r3, uint32_t addr) {
    asm volatile("ldmatrix.sync.aligned.m8n8.x4.shared.b16 {%0,%1,%2,%3}, [%4];"
        : "=r"(r0), "=r"(r1), "=r"(r2), "=r"(r3) : "r"(addr));
}
__device__ __forceinline__ void mma16816(float* d, uint32_t a0, uint32_t a1, uint32_t a2, uint32_t a3,
                                         uint32_t b0, uint32_t b1) {
    asm volatile("mma.sync.aligned.m16n8k16.row.col.f32.bf16.bf16.f32 "
        "{%0,%1,%2,%3}, {%4,%5,%6,%7}, {%8,%9}, {%0,%1,%2,%3};"
        : "+f"(d[0]), "+f"(d[1]), "+f"(d[2]), "+f"(d[3])
        : "r"(a0), "r"(a1), "r"(a2), "r"(a3), "r"(b0), "r"(b1));
}
__device__ __forceinline__ uint32_t sw128(uint32_t off) { return off ^ ((off >> 3) & 0x70); }

// ========================= conversion kernels =========================
// A' row r: [0,KK)=hi, [KK,2KK)=hi, [2KK,3KK)=lo  (rows 0..4095=input, 4096..8191=h_prev)
__global__ __launch_bounds__(256)
void convert_A(const float* __restrict__ input, const float* __restrict__ h_prev)
{
    size_t idx = (size_t)blockIdx.x * blockDim.x + threadIdx.x;   // pair index
    size_t e = idx * 2;
    size_t r = e / KK;
    int k = (int)(e % KK);
    const float* src = (r < MB) ? (input + r * KK) : (h_prev + (r - MB) * KK);
    float2 v = *reinterpret_cast<const float2*>(src + k);
    __nv_bfloat162 hi, lo;
    hi.x = __float2bfloat16_rn(v.x);
    hi.y = __float2bfloat16_rn(v.y);
    lo.x = __float2bfloat16_rn(v.x - __bfloat162float(hi.x));
    lo.y = __float2bfloat16_rn(v.y - __bfloat162float(hi.y));
    __nv_bfloat16* dst = g_Abig + r * KTOT;
    *reinterpret_cast<__nv_bfloat162*>(dst + k) = hi;
    *reinterpret_cast<__nv_bfloat162*>(dst + KK + k) = hi;
    *reinterpret_cast<__nv_bfloat162*>(dst + 2 * KK + k) = lo;
}

// Bt'[mat][n][*]: transpose of w[k][n]; segments [0,KK)=hi, [KK,2KK)=lo, [2KK,3KK)=hi
__global__ __launch_bounds__(256)
void convert_B(const float* __restrict__ w0, const float* __restrict__ w1)
{
    __shared__ float tile[32][33];
    const int mat = blockIdx.z;
    const float* w = mat ? w1 : w0;
    const int k0 = blockIdx.y * 32;
    const int n0 = blockIdx.x * 32;
    const int tx = threadIdx.x, ty = threadIdx.y;   // (32, 8)
    #pragma unroll
    for (int i = 0; i < 32; i += 8)
        tile[ty + i][tx] = w[(size_t)(k0 + ty + i) * NN + n0 + tx];
    __syncthreads();
    __nv_bfloat16* dst = g_Bbig[mat];
    #pragma unroll
    for (int i = 0; i < 32; i += 8) {
        int n = n0 + ty + i;
        int k = k0 + tx;
        float x = tile[tx][ty + i];
        __nv_bfloat16 hi = __float2bfloat16_rn(x);
        __nv_bfloat16 lo = __float2bfloat16_rn(x - __bfloat162float(hi));
        __nv_bfloat16* row = dst + (size_t)n * KTOT;
        row[k] = hi;
        row[KK + k] = lo;
        row[2 * KK + k] = hi;
    }
}

// ========================= mma.sync GEMM =========================
// C[128,128] tiles; A[MTOT,KTOT] row-major bf16, Bt[n][k] bf16 (K-major).
#define BM 128
#define BN 128
#define BK 64
#define GSTAGES 3
#define NSTEPS (KTOT / BK)             // 48
#define GTHREADS 256

#define A_STAGE_BYTES (BM * 128)       // 16384 (128B swizzled rows)
#define B_STAGE_BYTES (BN * 128)       // 16384
#define STAGE_BYTES (A_STAGE_BYTES + B_STAGE_BYTES)   // 32768
#define GSMEM_TOTAL (GSTAGES * STAGE_BYTES)           // 98304

__device__ __forceinline__ void load_stage(uint32_t sbase, int s, int kc, int tid,
                                           const __nv_bfloat16* gA, const __nv_bfloat16* gB)
{
    const int kbase = kc * BK;
    const uint32_t stage = sbase + s * STAGE_BYTES;
    #pragma unroll
    for (int j = 0; j < 8; j++) {
        int idx = tid + j * GTHREADS;   // 0..2047
        int row = (idx >> 3) & 127;
        int ch = idx & 7;
        uint32_t off = (uint32_t)(row * 128 + ch * 16);
        if (idx < 1024) {
            cp_async16(stage + sw128(off), gA + (size_t)row * KTOT + kbase + ch * 8);
        } else {
            cp_async16(stage + A_STAGE_BYTES + sw128(off), gB + (size_t)row * KTOT + kbase + ch * 8);
        }
    }
}

__global__ __launch_bounds__(GTHREADS, 1)
void gemm_bf16x3()
{
    extern __shared__ char gsm[];
    const uint32_t sbase = smem_u32(gsm);
    const int tid = threadIdx.x;
    const int wid = tid >> 5;
    const int lid = tid & 31;
    const int warp_m = wid >> 2;        // 0..1 -> 64-row slab
    const int warp_n = wid & 3;         // 0..3 -> 32-col slab

    const int tileN = blockIdx.x;       // 0..31
    const int tileM = blockIdx.y;       // 0..63
    const int mat = (tileM >= 32) ? 1 : 0;
    const __nv_bfloat16* gA = g_Abig + (size_t)tileM * BM * KTOT;
    const __nv_bfloat16* gB = g_Bbig[mat] + (size_t)tileN * BN * KTOT;

    float acc[4][4][4];
    #pragma unroll
    for (int mi = 0; mi < 4; mi++)
        #pragma unroll
        for (int ni = 0; ni < 4; ni++)
            #pragma unroll
            for (int r = 0; r < 4; r++)
                acc[mi][ni][r] = 0.0f;

    // prologue: fill first 2 stages
    load_stage(sbase, 0, 0, tid, gA, gB);
    CP_COMMIT();
    load_stage(sbase, 1, 1, tid, gA, gB);
    CP_COMMIT();

    // per-lane ldmatrix offsets (within a stage, unswizzled)
    // A: row = warp_m*64 + mi*16 + (l&15), kbyte = ks*32 + (l>>4)*16
    const int a_row_l = warp_m * 64 + (lid & 15);
    const int a_kb_l = (lid >> 4) * 16;
    // B: n = warp_n*32 + np*16 + ((l>>4)&1)*8 + (l&7), kbyte = ks*32 + ((l>>3)&1)*16
    const int b_row_l = warp_n * 32 + ((lid >> 4) & 1) * 8 + (lid & 7);
    const int b_kb_l = ((lid >> 3) & 1) * 16;

    for (int i = 0; i < NSTEPS; i++) {
        const int s = i % GSTAGES;
        CP_WAIT_GROUP(1);               // stage i complete
        __syncthreads();                // all warps done with stage being overwritten

        if (i + 2 < NSTEPS) {
            load_stage(sbase, (i + 2) % GSTAGES, i + 2, tid, gA, gB);
            CP_COMMIT();
        }

        const uint32_t aS = sbase + s * STAGE_BYTES;
        const uint32_t bS = aS + A_STAGE_BYTES;

        #pragma unroll
        for (int ks = 0; ks < 4; ks++) {
            uint32_t a[4][4];
            #pragma unroll
            for (int mi = 0; mi < 4; mi++) {
                uint32_t off = (uint32_t)((a_row_l + mi * 16) * 128 + ks * 32 + a_kb_l);
                ldsm_x4(a[mi][0], a[mi][1], a[mi][2], a[mi][3], aS + sw128(off));
            }
            uint32_t b[4][2];
            #pragma unroll
            for (int np = 0; np < 2; np++) {
                uint32_t off = (uint32_t)((b_row_l + np * 16) * 128 + ks * 32 + b_kb_l);
                uint32_t r0, r1, r2, r3;
                ldsm_x4(r0, r1, r2, r3, bS + sw128(off));
                b[np * 2][0] = r0; b[np * 2][1] = r1;
                b[np * 2 + 1][0] = r2; b[np * 2 + 1][1] = r3;
            }
            #pragma unroll
            for (int mi = 0; mi < 4; mi++)
                #pragma unroll
                for (int ni = 0; ni < 4; ni++)
                    mma16816(acc[mi][ni], a[mi][0], a[mi][1], a[mi][2], a[mi][3],
                             b[ni][0], b[ni][1]);
        }
    }

    // store C
    float* gC = ((tileM < 32) ? (g_pre_i2h + (size_t)tileM * BM * NN)
                              : (g_pre_h2h + (size_t)(tileM - 32) * BM * NN))
                + (size_t)tileN * BN;
    const int mrow = warp_m * 64 + (lid >> 2);
    const int ncol = warp_n * 32 + (lid & 3) * 2;
    #pragma unroll
    for (int mi = 0; mi < 4; mi++) {
        #pragma unroll
        for (int ni = 0; ni < 4; ni++) {
            float* p0 = gC + (size_t)(mrow + mi * 16) * NN + ncol + ni * 8;
            float* p1 = gC + (size_t)(mrow + mi * 16 + 8) * NN + ncol + ni * 8;
            *reinterpret_cast<float2*>(p0) = make_float2(acc[mi][ni][0], acc[mi][ni][1]);
            *reinterpret_cast<float2*>(p1) = make_float2(acc[mi][ni][2], acc[mi][ni][3]);
        }
    }
}

// ========================= LN + gates epilogue =========================
#define EPS 1e-6f

__device__ __forceinline__ float sigm(float x) { return 1.0f / (1.0f + expf(-x)); }

__device__ void block_reduce2(float& s, float& q)
{
    __shared__ float rs[8], rq[8];
    __shared__ float bs, bq;
    #pragma unroll
    for (int o = 16; o > 0; o >>= 1) {
        s += __shfl_down_sync(0xffffffffu, s, o);
        q += __shfl_down_sync(0xffffffffu, q, o);
    }
    const int w = threadIdx.x >> 5, l = threadIdx.x & 31;
    __syncthreads();
    if (l == 0) { rs[w] = s; rq[w] = q; }
    __syncthreads();
    if (threadIdx.x == 0) {
        float a = 0.0f, b = 0.0f;
        #pragma unroll
        for (int i = 0; i < 8; i++) { a += rs[i]; b += rq[i]; }
        bs = a; bq = b;
    }
    __syncthreads();
    s = bs; q = bq;
}

__global__ __launch_bounds__(256)
void lstm_epilogue(const float* __restrict__ c_prev,
                   const float* __restrict__ b_i2h, const float* __restrict__ b_h2h,
                   const float* __restrict__ g_i2h, const float* __restrict__ be_i2h,
                   const float* __restrict__ g_h2h, const float* __restrict__ be_h2h,
                   const float* __restrict__ g_c,   const float* __restrict__ be_c,
                   float* __restrict__ out)
{
    __shared__ float sh_g[NN];
    __shared__ float sh_h[NN];

    const int r = blockIdx.x;
    const int tid = threadIdx.x;
    const float* hi = g_pre_i2h + (size_t)r * NN;
    const float* hh = g_pre_h2h + (size_t)r * NN;

    float s = 0.0f, q = 0.0f;
    for (int j = tid; j < NN; j += 256) {
        float v = hi[j] + b_i2h[j];
        sh_g[j] = v;
        s += v; q += v * v;
    }
    block_reduce2(s, q);
    const float m1 = s / (float)NN;
    const float v1 = (q - s * s / (float)NN) / (float)(NN - 1);
    const float inv1 = 1.0f / (sqrtf(v1) + EPS);

    s = 0.0f; q = 0.0f;
    for (int j = tid; j < NN; j += 256) {
        float v = hh[j] + b_h2h[j];
        sh_h[j] = v;
        s += v; q += v * v;
    }
    block_reduce2(s, q);
    const float m2 = s / (float)NN;
    const float v2 = (q - s * s / (float)NN) / (float)(NN - 1);
    const float inv2 = 1.0f / (sqrtf(v2) + EPS);

    for (int j = tid; j < NN; j += 256) {
        float a = g_i2h[j] * ((sh_g[j] - m1) * inv1) + be_i2h[j];
        float b = g_h2h[j] * ((sh_h[j] - m2) * inv2) + be_h2h[j];
        sh_g[j] = a + b;
    }
    __syncthreads();

    s = 0.0f; q = 0.0f;
    for (int k = tid; k < HH; k += 256) {
        float ig = sh_g[k];
        float fg = sh_g[HH + k];
        float ug = sh_g[2 * HH + k];
        float og = sh_g[3 * HH + k];
        float cp = c_prev[(size_t)r * HH + k] * sigm(fg + 1.0f) + tanhf(ug) * sigm(ig);
        sh_h[k] = cp;
        sh_h[HH + k] = og;
        s += cp; q += cp * cp;
    }
    block_reduce2(s, q);
    const float m3 = s / (float)HH;
    const float v3 = (q - s * s / (float)HH) / (float)(HH - 1);
    const float inv3 = 1.0f / (sqrtf(v3) + EPS);

    float* out_h = out;
    float* out_c = out + (size_t)MB * HH;
    for (int k = tid; k < HH; k += 256) {
        float c = g_c[k] * ((sh_h[k] - m3) * inv3) + be_c[k];
        float h = sigm(sh_h[HH + k]) * tanhf(c);
        out_h[(size_t)r * HH + k] = h;
        out_c[(size_t)r * HH + k] = c;
    }
}

// ========================= launch =========================
extern "C" void kernel_launch(void* const* d_in, const int* in_sizes, int n_in,
                              void* d_out, int out_size)
{
    const float* input  = (const float*)d_in[0];
    const float* h_prev = (const float*)d_in[1];
    const float* c_prev = (const float*)d_in[2];
    const float* w_i2h  = (const float*)d_in[3];
    const float* b_i2h  = (const float*)d_in[4];
    const float* w_h2h  = (const float*)d_in[5];
    const float* b_h2h  = (const float*)d_in[6];
    const float* g_i2h  = (const float*)d_in[7];
    const float* be_i2h = (const float*)d_in[8];
    const float* g_h2h  = (const float*)d_in[9];
    const float* be_h2h = (const float*)d_in[10];
    const float* g_c    = (const float*)d_in[11];
    const float* be_c   = (const float*)d_in[12];
    float* out = (float*)d_out;

    cudaFuncSetAttribute(gemm_bf16x3, cudaFuncAttributeMaxDynamicSharedMemorySize, GSMEM_TOTAL);

    // split-bf16 operand prep
    convert_A<<<(MTOT * KK / 2) / 256, 256>>>(input, h_prev);
    convert_B<<<dim3(NN / 32, KK / 32, 2), dim3(32, 8)>>>(w_i2h, w_h2h);

    // fused dual GEMM on HMMA (K'=3072 covers hi*hi + hi*lo + lo*hi)
    gemm_bf16x3<<<dim3(NN / BN, MTOT / BM), GTHREADS, GSMEM_TOTAL>>>();

    lstm_epilogue<<<MB, 256>>>(c_prev, b_i2h, b_h2h, g_i2h, be_i2h,
                               g_h2h, be_h2h, g_c, be_c, out);
}

// round 8
// speedup vs baseline: 2.8246x; 1.2210x over previous
#include <cuda_runtime.h>
#include <cuda_bf16.h>
#include <math.h>
#include <stdint.h>

// Problem constants (B=4096, I=H=1024, 4H=4096)
#define MB 4096
#define KK 1024
#define NN 4096
#define HH 1024
#define MTOT 8192              // input rows stacked on h_prev rows
#define KTOT 3072              // 3 * KK  (split-bf16 segments)

// ---------------- scratch (allocation-free: device globals) ----------------
__device__ __align__(1024) __nv_bfloat16 g_Abig[(size_t)MTOT * KTOT];      // 48 MB
__device__ __align__(1024) __nv_bfloat16 g_Bbig[2][(size_t)NN * KTOT];     // 48 MB
__device__ float g_pre_i2h[(size_t)MB * NN];                               // 64 MB
__device__ float g_pre_h2h[(size_t)MB * NN];                               // 64 MB

// ========================= PTX helpers =========================
__device__ __forceinline__ uint32_t smem_u32(const void* p) {
    uint32_t a;
    asm("{ .reg .u64 t; cvta.to.shared.u64 t, %1; cvt.u32.u64 %0, t; }" : "=r"(a) : "l"(p));
    return a;
}
__device__ __forceinline__ void cp_async16(uint32_t saddr, const void* gaddr) {
    asm volatile("cp.async.cg.shared.global [%0], [%1], 16;" :: "r"(saddr), "l"(gaddr));
}
#define CP_COMMIT() asm volatile("cp.async.commit_group;" ::: "memory")
#define CP_WAIT_GROUP(n) asm volatile("cp.async.wait_group %0;" :: "n"(n) : "memory")

__device__ __forceinline__ void ldsm_x4(uint32_t& r0, uint32_t& r1, uint32_t& r2, uint32_t& r3, uint32_t addr) {
    asm volatile("ldmatrix.sync.aligned.m8n8.x4.shared.b16 {%0,%1,%2,%3}, [%4];"
        : "=r"(r0), "=r"(r1), "=r"(r2), "=r"(r3) : "r"(addr));
}
__device__ __forceinline__ void mma16816(float* d, uint32_t a0, uint32_t a1, uint32_t a2, uint32_t a3,
                                         uint32_t b0, uint32_t b1) {
    asm volatile("mma.sync.aligned.m16n8k16.row.col.f32.bf16.bf16.f32 "
        "{%0,%1,%2,%3}, {%4,%5,%6,%7}, {%8,%9}, {%0,%1,%2,%3};"
        : "+f"(d[0]), "+f"(d[1]), "+f"(d[2]), "+f"(d[3])
        : "r"(a0), "r"(a1), "r"(a2), "r"(a3), "r"(b0), "r"(b1));
}
__device__ __forceinline__ uint32_t sw128(uint32_t off) { return off ^ ((off >> 3) & 0x70); }

// ========================= conversion kernels =========================
// A' row r: [0,KK)=hi, [KK,2KK)=hi, [2KK,3KK)=lo  (rows 0..4095=input, 4096..8191=h_prev)
__global__ __launch_bounds__(256)
void convert_A(const float* __restrict__ input, const float* __restrict__ h_prev)
{
    size_t idx = (size_t)blockIdx.x * blockDim.x + threadIdx.x;   // pair index
    size_t e = idx * 2;
    size_t r = e / KK;
    int k = (int)(e % KK);
    const float* src = (r < MB) ? (input + r * KK) : (h_prev + (r - MB) * KK);
    float2 v = *reinterpret_cast<const float2*>(src + k);
    __nv_bfloat162 hi, lo;
    hi.x = __float2bfloat16_rn(v.x);
    hi.y = __float2bfloat16_rn(v.y);
    lo.x = __float2bfloat16_rn(v.x - __bfloat162float(hi.x));
    lo.y = __float2bfloat16_rn(v.y - __bfloat162float(hi.y));
    __nv_bfloat16* dst = g_Abig + r * KTOT;
    *reinterpret_cast<__nv_bfloat162*>(dst + k) = hi;
    *reinterpret_cast<__nv_bfloat162*>(dst + KK + k) = hi;
    *reinterpret_cast<__nv_bfloat162*>(dst + 2 * KK + k) = lo;
}

// Bt'[mat][n][*]: transpose of w[k][n]; segments [0,KK)=hi, [KK,2KK)=lo, [2KK,3KK)=hi
__global__ __launch_bounds__(256)
void convert_B(const float* __restrict__ w0, const float* __restrict__ w1)
{
    __shared__ float tile[32][33];
    const int mat = blockIdx.z;
    const float* w = mat ? w1 : w0;
    const int k0 = blockIdx.y * 32;
    const int n0 = blockIdx.x * 32;
    const int tx = threadIdx.x, ty = threadIdx.y;   // (32, 8)
    #pragma unroll
    for (int i = 0; i < 32; i += 8)
        tile[ty + i][tx] = w[(size_t)(k0 + ty + i) * NN + n0 + tx];
    __syncthreads();
    __nv_bfloat16* dst = g_Bbig[mat];
    #pragma unroll
    for (int i = 0; i < 32; i += 8) {
        int n = n0 + ty + i;
        int k = k0 + tx;
        float x = tile[tx][ty + i];
        __nv_bfloat16 hi = __float2bfloat16_rn(x);
        __nv_bfloat16 lo = __float2bfloat16_rn(x - __bfloat162float(hi));
        __nv_bfloat16* row = dst + (size_t)n * KTOT;
        row[k] = hi;
        row[KK + k] = lo;
        row[2 * KK + k] = hi;
    }
}

// ========================= mma.sync GEMM =========================
// C[128,256] tiles; A[MTOT,KTOT] row-major bf16, Bt[n][k] bf16 (K-major).
#define BM 128
#define BN 256
#define BK 64
#define GSTAGES 3
#define NSTEPS (KTOT / BK)             // 48
#define GTHREADS 256

#define A_STAGE_BYTES (BM * 128)       // 16384 (128B swizzled rows)
#define B_STAGE_BYTES (BN * 128)       // 32768
#define STAGE_BYTES (A_STAGE_BYTES + B_STAGE_BYTES)   // 49152
#define GSMEM_TOTAL (GSTAGES * STAGE_BYTES)           // 147456

__device__ __forceinline__ void load_stage(uint32_t sbase, int s, int kc, int tid,
                                           const __nv_bfloat16* gA, const __nv_bfloat16* gB)
{
    const int kbase = kc * BK;
    const uint32_t stage = sbase + s * STAGE_BYTES;
    #pragma unroll
    for (int j = 0; j < 12; j++) {
        int idx = tid + j * GTHREADS;   // 0..3071
        if (idx < 1024) {               // A: 128 rows x 8 x 16B
            int row = idx >> 3, ch = idx & 7;
            uint32_t off = (uint32_t)(row * 128 + ch * 16);
            cp_async16(stage + sw128(off), gA + (size_t)row * KTOT + kbase + ch * 8);
        } else {                        // B: 256 rows x 8 x 16B
            int b = idx - 1024;
            int row = b >> 3, ch = b & 7;
            uint32_t off = (uint32_t)(row * 128 + ch * 16);
            cp_async16(stage + A_STAGE_BYTES + sw128(off), gB + (size_t)row * KTOT + kbase + ch * 8);
        }
    }
}

__global__ __launch_bounds__(GTHREADS, 1)
void gemm_bf16x3()
{
    extern __shared__ char gsm[];
    const uint32_t sbase = smem_u32(gsm);
    const int tid = threadIdx.x;
    const int wid = tid >> 5;
    const int lid = tid & 31;
    const int warp_m = wid >> 2;        // 0..1 -> 64-row slab
    const int warp_n = wid & 3;         // 0..3 -> 64-col slab

    const int tileN = blockIdx.x;       // 0..15
    const int tileM = blockIdx.y;       // 0..63
    const int mat = (tileM >= 32) ? 1 : 0;
    const __nv_bfloat16* gA = g_Abig + (size_t)tileM * BM * KTOT;
    const __nv_bfloat16* gB = g_Bbig[mat] + (size_t)tileN * BN * KTOT;

    float acc[4][8][4];
    #pragma unroll
    for (int mi = 0; mi < 4; mi++)
        #pragma unroll
        for (int ni = 0; ni < 8; ni++)
            #pragma unroll
            for (int r = 0; r < 4; r++)
                acc[mi][ni][r] = 0.0f;

    // prologue: fill first 2 stages
    load_stage(sbase, 0, 0, tid, gA, gB);
    CP_COMMIT();
    load_stage(sbase, 1, 1, tid, gA, gB);
    CP_COMMIT();

    // per-lane ldmatrix offsets (within a stage, unswizzled)
    const int a_row_l = warp_m * 64 + (lid & 15);
    const int a_kb_l = (lid >> 4) * 16;
    const int b_row_l = warp_n * 64 + ((lid >> 4) & 1) * 8 + (lid & 7);
    const int b_kb_l = ((lid >> 3) & 1) * 16;

    for (int i = 0; i < NSTEPS; i++) {
        const int s = i % GSTAGES;
        CP_WAIT_GROUP(1);               // stage i complete
        __syncthreads();                // all warps done with stage being overwritten

        if (i + 2 < NSTEPS) {
            load_stage(sbase, (i + 2) % GSTAGES, i + 2, tid, gA, gB);
            CP_COMMIT();
        }

        const uint32_t aS = sbase + s * STAGE_BYTES;
        const uint32_t bS = aS + A_STAGE_BYTES;

        #pragma unroll
        for (int ks = 0; ks < 4; ks++) {
            uint32_t a[4][4];
            #pragma unroll
            for (int mi = 0; mi < 4; mi++) {
                uint32_t off = (uint32_t)((a_row_l + mi * 16) * 128 + ks * 32 + a_kb_l);
                ldsm_x4(a[mi][0], a[mi][1], a[mi][2], a[mi][3], aS + sw128(off));
            }
            uint32_t b[8][2];
            #pragma unroll
            for (int np = 0; np < 4; np++) {
                uint32_t off = (uint32_t)((b_row_l + np * 16) * 128 + ks * 32 + b_kb_l);
                uint32_t r0, r1, r2, r3;
                ldsm_x4(r0, r1, r2, r3, bS + sw128(off));
                b[np * 2][0] = r0; b[np * 2][1] = r1;
                b[np * 2 + 1][0] = r2; b[np * 2 + 1][1] = r3;
            }
            #pragma unroll
            for (int mi = 0; mi < 4; mi++)
                #pragma unroll
                for (int ni = 0; ni < 8; ni++)
                    mma16816(acc[mi][ni], a[mi][0], a[mi][1], a[mi][2], a[mi][3],
                             b[ni][0], b[ni][1]);
        }
    }

    // store C
    float* gC = ((tileM < 32) ? (g_pre_i2h + (size_t)tileM * BM * NN)
                              : (g_pre_h2h + (size_t)(tileM - 32) * BM * NN))
                + (size_t)tileN * BN;
    const int mrow = warp_m * 64 + (lid >> 2);
    const int ncol = warp_n * 64 + (lid & 3) * 2;
    #pragma unroll
    for (int mi = 0; mi < 4; mi++) {
        #pragma unroll
        for (int ni = 0; ni < 8; ni++) {
            float* p0 = gC + (size_t)(mrow + mi * 16) * NN + ncol + ni * 8;
            float* p1 = gC + (size_t)(mrow + mi * 16 + 8) * NN + ncol + ni * 8;
            *reinterpret_cast<float2*>(p0) = make_float2(acc[mi][ni][0], acc[mi][ni][1]);
            *reinterpret_cast<float2*>(p1) = make_float2(acc[mi][ni][2], acc[mi][ni][3]);
        }
    }
}

// ========================= LN + gates epilogue =========================
#define EPS 1e-6f

__device__ __forceinline__ float sigm(float x) { return 1.0f / (1.0f + __expf(-x)); }
__device__ __forceinline__ float fast_tanh(float x) {
    float ax = fminf(fabsf(x), 15.0f);
    float t = __expf(2.0f * ax);
    float r = (t - 1.0f) / (t + 1.0f);
    return copysignf(r, x);
}

__device__ void block_reduce2(float& s, float& q)
{
    __shared__ __align__(16) float rs[8], rq[8];
    __shared__ float bs, bq;
    #pragma unroll
    for (int o = 16; o > 0; o >>= 1) {
        s += __shfl_down_sync(0xffffffffu, s, o);
        q += __shfl_down_sync(0xffffffffu, q, o);
    }
    const int w = threadIdx.x >> 5, l = threadIdx.x & 31;
    __syncthreads();
    if (l == 0) { rs[w] = s; rq[w] = q; }
    __syncthreads();
    if (threadIdx.x == 0) {
        float a = 0.0f, b = 0.0f;
        #pragma unroll
        for (int i = 0; i < 8; i++) { a += rs[i]; b += rq[i]; }
        bs = a; bq = b;
    }
    __syncthreads();
    s = bs; q = bq;
}

__global__ __launch_bounds__(256)
void lstm_epilogue(const float* __restrict__ c_prev,
                   const float* __restrict__ b_i2h, const float* __restrict__ b_h2h,
                   const float* __restrict__ g_i2h, const float* __restrict__ be_i2h,
                   const float* __restrict__ g_h2h, const float* __restrict__ be_h2h,
                   const float* __restrict__ g_c,   const float* __restrict__ be_c,
                   float* __restrict__ out)
{
    __shared__ __align__(16) float sh_g[NN];
    __shared__ __align__(16) float sh_h[NN];

    const int r = blockIdx.x;
    const int tid = threadIdx.x;
    const float* hi = g_pre_i2h + (size_t)r * NN;
    const float* hh = g_pre_h2h + (size_t)r * NN;

    // --- LN stats for i2h row (float4) ---
    float s = 0.0f, q = 0.0f;
    for (int j = tid * 4; j < NN; j += 1024) {
        float4 v = *reinterpret_cast<const float4*>(hi + j);
        float4 b = *reinterpret_cast<const float4*>(b_i2h + j);
        v.x += b.x; v.y += b.y; v.z += b.z; v.w += b.w;
        *reinterpret_cast<float4*>(sh_g + j) = v;
        s += v.x + v.y + v.z + v.w;
        q += v.x * v.x + v.y * v.y + v.z * v.z + v.w * v.w;
    }
    block_reduce2(s, q);
    const float m1 = s / (float)NN;
    const float v1 = (q - s * s / (float)NN) / (float)(NN - 1);
    const float inv1 = 1.0f / (sqrtf(v1) + EPS);

    // --- LN stats for h2h row ---
    s = 0.0f; q = 0.0f;
    for (int j = tid * 4; j < NN; j += 1024) {
        float4 v = *reinterpret_cast<const float4*>(hh + j);
        float4 b = *reinterpret_cast<const float4*>(b_h2h + j);
        v.x += b.x; v.y += b.y; v.z += b.z; v.w += b.w;
        *reinterpret_cast<float4*>(sh_h + j) = v;
        s += v.x + v.y + v.z + v.w;
        q += v.x * v.x + v.y * v.y + v.z * v.z + v.w * v.w;
    }
    block_reduce2(s, q);
    const float m2 = s / (float)NN;
    const float v2 = (q - s * s / (float)NN) / (float)(NN - 1);
    const float inv2 = 1.0f / (sqrtf(v2) + EPS);

    // --- normalized sum -> gates ---
    for (int j = tid * 4; j < NN; j += 1024) {
        float4 x = *reinterpret_cast<const float4*>(sh_g + j);
        float4 y = *reinterpret_cast<const float4*>(sh_h + j);
        float4 ga = *reinterpret_cast<const float4*>(g_i2h + j);
        float4 ba = *reinterpret_cast<const float4*>(be_i2h + j);
        float4 gb = *reinterpret_cast<const float4*>(g_h2h + j);
        float4 bb = *reinterpret_cast<const float4*>(be_h2h + j);
        float4 o;
        o.x = ga.x * ((x.x - m1) * inv1) + ba.x + gb.x * ((y.x - m2) * inv2) + bb.x;
        o.y = ga.y * ((x.y - m1) * inv1) + ba.y + gb.y * ((y.y - m2) * inv2) + bb.y;
        o.z = ga.z * ((x.z - m1) * inv1) + ba.z + gb.z * ((y.z - m2) * inv2) + bb.z;
        o.w = ga.w * ((x.w - m1) * inv1) + ba.w + gb.w * ((y.w - m2) * inv2) + bb.w;
        *reinterpret_cast<float4*>(sh_g + j) = o;
    }
    __syncthreads();

    // --- cell pre-activation ---
    s = 0.0f; q = 0.0f;
    for (int k = tid * 4; k < HH; k += 1024) {
        float4 ig = *reinterpret_cast<const float4*>(sh_g + k);
        float4 fg = *reinterpret_cast<const float4*>(sh_g + HH + k);
        float4 ug = *reinterpret_cast<const float4*>(sh_g + 2 * HH + k);
        float4 og = *reinterpret_cast<const float4*>(sh_g + 3 * HH + k);
        float4 cv = *reinterpret_cast<const float4*>(c_prev + (size_t)r * HH + k);
        float4 cp;
        cp.x = cv.x * sigm(fg.x + 1.0f) + fast_tanh(ug.x) * sigm(ig.x);
        cp.y = cv.y * sigm(fg.y + 1.0f) + fast_tanh(ug.y) * sigm(ig.y);
        cp.z = cv.z * sigm(fg.z + 1.0f) + fast_tanh(ug.z) * sigm(ig.z);
        cp.w = cv.w * sigm(fg.w + 1.0f) + fast_tanh(ug.w) * sigm(ig.w);
        *reinterpret_cast<float4*>(sh_h + k) = cp;
        *reinterpret_cast<float4*>(sh_h + HH + k) = og;
        s += cp.x + cp.y + cp.z + cp.w;
        q += cp.x * cp.x + cp.y * cp.y + cp.z * cp.z + cp.w * cp.w;
    }
    block_reduce2(s, q);
    const float m3 = s / (float)HH;
    const float v3 = (q - s * s / (float)HH) / (float)(HH - 1);
    const float inv3 = 1.0f / (sqrtf(v3) + EPS);

    // --- c = LN(cpre), h = sigmoid(o) * tanh(c) ---
    float* out_h = out;
    float* out_c = out + (size_t)MB * HH;
    for (int k = tid * 4; k < HH; k += 1024) {
        float4 cp = *reinterpret_cast<const float4*>(sh_h + k);
        float4 og = *reinterpret_cast<const float4*>(sh_h + HH + k);
        float4 gc = *reinterpret_cast<const float4*>(g_c + k);
        float4 bc = *reinterpret_cast<const float4*>(be_c + k);
        float4 c, h;
        c.x = gc.x * ((cp.x - m3) * inv3) + bc.x;
        c.y = gc.y * ((cp.y - m3) * inv3) + bc.y;
        c.z = gc.z * ((cp.z - m3) * inv3) + bc.z;
        c.w = gc.w * ((cp.w - m3) * inv3) + bc.w;
        h.x = sigm(og.x) * fast_tanh(c.x);
        h.y = sigm(og.y) * fast_tanh(c.y);
        h.z = sigm(og.z) * fast_tanh(c.z);
        h.w = sigm(og.w) * fast_tanh(c.w);
        *reinterpret_cast<float4*>(out_h + (size_t)r * HH + k) = h;
        *reinterpret_cast<float4*>(out_c + (size_t)r * HH + k) = c;
    }
}

// ========================= launch =========================
extern "C" void kernel_launch(void* const* d_in, const int* in_sizes, int n_in,
                              void* d_out, int out_size)
{
    const float* input  = (const float*)d_in[0];
    const float* h_prev = (const float*)d_in[1];
    const float* c_prev = (const float*)d_in[2];
    const float* w_i2h  = (const float*)d_in[3];
    const float* b_i2h  = (const float*)d_in[4];
    const float* w_h2h  = (const float*)d_in[5];
    const float* b_h2h  = (const float*)d_in[6];
    const float* g_i2h  = (const float*)d_in[7];
    const float* be_i2h = (const float*)d_in[8];
    const float* g_h2h  = (const float*)d_in[9];
    const float* be_h2h = (const float*)d_in[10];
    const float* g_c    = (const float*)d_in[11];
    const float* be_c   = (const float*)d_in[12];
    float* out = (float*)d_out;

    cudaFuncSetAttribute(gemm_bf16x3, cudaFuncAttributeMaxDynamicSharedMemorySize, GSMEM_TOTAL);

    // split-bf16 operand prep
    convert_A<<<(MTOT * KK / 2) / 256, 256>>>(input, h_prev);
    convert_B<<<dim3(NN / 32, KK / 32, 2), dim3(32, 8)>>>(w_i2h, w_h2h);

    // fused dual GEMM on HMMA (K'=3072 covers hi*hi + hi*lo + lo*hi)
    gemm_bf16x3<<<dim3(NN / BN, MTOT / BM), GTHREADS, GSMEM_TOTAL>>>();

    lstm_epilogue<<<MB, 256>>>(c_prev, b_i2h, b_h2h, g_i2h, be_i2h,
                               g_h2h, be_h2h, g_c, be_c, out);
}

// round 9
// speedup vs baseline: 2.8545x; 1.0106x over previous
#include <cuda_runtime.h>
#include <cuda_bf16.h>
#include <math.h>
#include <stdint.h>

// Problem constants (B=4096, I=H=1024, 4H=4096)
#define MB 4096
#define KK 1024
#define NN 4096
#define HH 1024
#define MTOT 8192              // input rows stacked on h_prev rows
#define KTOT 3072              // 3 * KK  (split-bf16 segments)

// ---------------- scratch (allocation-free: device globals) ----------------
__device__ __align__(1024) __nv_bfloat16 g_Abig[(size_t)MTOT * KTOT];      // 48 MB
__device__ __align__(1024) __nv_bfloat16 g_Bbig[2][(size_t)NN * KTOT];     // 48 MB
__device__ float g_pre_i2h[(size_t)MB * NN];                               // 64 MB
__device__ float g_pre_h2h[(size_t)MB * NN];                               // 64 MB

// ========================= PTX helpers =========================
__device__ __forceinline__ uint32_t smem_u32(const void* p) {
    uint32_t a;
    asm("{ .reg .u64 t; cvta.to.shared.u64 t, %1; cvt.u32.u64 %0, t; }" : "=r"(a) : "l"(p));
    return a;
}
__device__ __forceinline__ void cp_async16(uint32_t saddr, const void* gaddr) {
    asm volatile("cp.async.cg.shared.global [%0], [%1], 16;" :: "r"(saddr), "l"(gaddr));
}
#define CP_COMMIT() asm volatile("cp.async.commit_group;" ::: "memory")
#define CP_WAIT_GROUP(n) asm volatile("cp.async.wait_group %0;" :: "n"(n) : "memory")

__device__ __forceinline__ void ldsm_x4(uint32_t& r0, uint32_t& r1, uint32_t& r2, uint32_t& r3, uint32_t addr) {
    asm volatile("ldmatrix.sync.aligned.m8n8.x4.shared.b16 {%0,%1,%2,%3}, [%4];"
        : "=r"(r0), "=r"(r1), "=r"(r2), "=r"(r3) : "r"(addr));
}
__device__ __forceinline__ void mma16816(float* d, uint32_t a0, uint32_t a1, uint32_t a2, uint32_t a3,
                                         uint32_t b0, uint32_t b1) {
    asm volatile("mma.sync.aligned.m16n8k16.row.col.f32.bf16.bf16.f32 "
        "{%0,%1,%2,%3}, {%4,%5,%6,%7}, {%8,%9}, {%0,%1,%2,%3};"
        : "+f"(d[0]), "+f"(d[1]), "+f"(d[2]), "+f"(d[3])
        : "r"(a0), "r"(a1), "r"(a2), "r"(a3), "r"(b0), "r"(b1));
}
__device__ __forceinline__ uint32_t sw128(uint32_t off) { return off ^ ((off >> 3) & 0x70); }

// ========================= conversion kernels =========================
// A' row r: [0,KK)=hi, [KK,2KK)=hi, [2KK,3KK)=lo  (rows 0..4095=input, 4096..8191=h_prev)
__global__ __launch_bounds__(256)
void convert_A(const float* __restrict__ input, const float* __restrict__ h_prev)
{
    size_t idx = (size_t)blockIdx.x * blockDim.x + threadIdx.x;   // pair index
    size_t e = idx * 2;
    size_t r = e / KK;
    int k = (int)(e % KK);
    const float* src = (r < MB) ? (input + r * KK) : (h_prev + (r - MB) * KK);
    float2 v = *reinterpret_cast<const float2*>(src + k);
    __nv_bfloat162 hi, lo;
    hi.x = __float2bfloat16_rn(v.x);
    hi.y = __float2bfloat16_rn(v.y);
    lo.x = __float2bfloat16_rn(v.x - __bfloat162float(hi.x));
    lo.y = __float2bfloat16_rn(v.y - __bfloat162float(hi.y));
    __nv_bfloat16* dst = g_Abig + r * KTOT;
    *reinterpret_cast<__nv_bfloat162*>(dst + k) = hi;
    *reinterpret_cast<__nv_bfloat162*>(dst + KK + k) = hi;
    *reinterpret_cast<__nv_bfloat162*>(dst + 2 * KK + k) = lo;
}

// Bt'[mat][n][*]: transpose of w[k][n]; segments [0,KK)=hi, [KK,2KK)=lo, [2KK,3KK)=hi
__global__ __launch_bounds__(256)
void convert_B(const float* __restrict__ w0, const float* __restrict__ w1)
{
    __shared__ float tile[32][33];
    const int mat = blockIdx.z;
    const float* w = mat ? w1 : w0;
    const int k0 = blockIdx.y * 32;
    const int n0 = blockIdx.x * 32;
    const int tx = threadIdx.x, ty = threadIdx.y;   // (32, 8)
    #pragma unroll
    for (int i = 0; i < 32; i += 8)
        tile[ty + i][tx] = w[(size_t)(k0 + ty + i) * NN + n0 + tx];
    __syncthreads();
    __nv_bfloat16* dst = g_Bbig[mat];
    #pragma unroll
    for (int i = 0; i < 32; i += 8) {
        int n = n0 + ty + i;
        int k = k0 + tx;
        float x = tile[tx][ty + i];
        __nv_bfloat16 hi = __float2bfloat16_rn(x);
        __nv_bfloat16 lo = __float2bfloat16_rn(x - __bfloat162float(hi));
        __nv_bfloat16* row = dst + (size_t)n * KTOT;
        row[k] = hi;
        row[KK + k] = lo;
        row[2 * KK + k] = hi;
    }
}

// ========================= mma.sync GEMM =========================
// C[128,256] tiles; A[MTOT,KTOT] row-major bf16, Bt[n][k] bf16 (K-major).
#define BM 128
#define BN 256
#define BK 64
#define GSTAGES 4
#define NSTEPS (KTOT / BK)             // 48
#define GTHREADS 256

#define A_STAGE_BYTES (BM * 128)       // 16384 (128B swizzled rows)
#define B_STAGE_BYTES (BN * 128)       // 32768
#define STAGE_BYTES (A_STAGE_BYTES + B_STAGE_BYTES)   // 49152
#define GSMEM_TOTAL (GSTAGES * STAGE_BYTES)           // 196608

__device__ __forceinline__ void load_stage(uint32_t sbase, int s, int kc, int tid,
                                           const __nv_bfloat16* gA, const __nv_bfloat16* gB)
{
    const int kbase = kc * BK;
    const uint32_t stage = sbase + s * STAGE_BYTES;
    #pragma unroll
    for (int j = 0; j < 12; j++) {
        int idx = tid + j * GTHREADS;   // 0..3071
        if (idx < 1024) {               // A: 128 rows x 8 x 16B
            int row = idx >> 3, ch = idx & 7;
            uint32_t off = (uint32_t)(row * 128 + ch * 16);
            cp_async16(stage + sw128(off), gA + (size_t)row * KTOT + kbase + ch * 8);
        } else {                        // B: 256 rows x 8 x 16B
            int b = idx - 1024;
            int row = b >> 3, ch = b & 7;
            uint32_t off = (uint32_t)(row * 128 + ch * 16);
            cp_async16(stage + A_STAGE_BYTES + sw128(off), gB + (size_t)row * KTOT + kbase + ch * 8);
        }
    }
}

__global__ __launch_bounds__(GTHREADS, 1)
void gemm_bf16x3()
{
    extern __shared__ char gsm[];
    const uint32_t sbase = smem_u32(gsm);
    const int tid = threadIdx.x;
    const int wid = tid >> 5;
    const int lid = tid & 31;
    const int warp_m = wid >> 2;        // 0..1 -> 64-row slab
    const int warp_n = wid & 3;         // 0..3 -> 64-col slab

    const int tileN = blockIdx.x;       // 0..15
    const int tileM = blockIdx.y;       // 0..63
    const int mat = (tileM >= 32) ? 1 : 0;
    const __nv_bfloat16* gA = g_Abig + (size_t)tileM * BM * KTOT;
    const __nv_bfloat16* gB = g_Bbig[mat] + (size_t)tileN * BN * KTOT;

    float acc[4][8][4];
    #pragma unroll
    for (int mi = 0; mi < 4; mi++)
        #pragma unroll
        for (int ni = 0; ni < 8; ni++)
            #pragma unroll
            for (int r = 0; r < 4; r++)
                acc[mi][ni][r] = 0.0f;

    // prologue: fill first 3 stages (one commit group each)
    load_stage(sbase, 0, 0, tid, gA, gB);
    CP_COMMIT();
    load_stage(sbase, 1, 1, tid, gA, gB);
    CP_COMMIT();
    load_stage(sbase, 2, 2, tid, gA, gB);
    CP_COMMIT();

    // per-lane ldmatrix offsets (within a stage, unswizzled)
    const int a_row_l = warp_m * 64 + (lid & 15);
    const int a_kb_l = (lid >> 4) * 16;
    const int b_row_l = warp_n * 64 + ((lid >> 4) & 1) * 8 + (lid & 7);
    const int b_kb_l = ((lid >> 3) & 1) * 16;

    for (int i = 0; i < NSTEPS; i++) {
        const int s = i & 3;
        // Exactly one group is committed per iteration (empty in the tail),
        // so waiting for <=2 outstanding guarantees stage i's group is done.
        CP_WAIT_GROUP(2);
        __syncthreads();                // all warps finished reading the slot being refilled

        if (i + 3 < NSTEPS)
            load_stage(sbase, (i + 3) & 3, i + 3, tid, gA, gB);
        CP_COMMIT();                    // uniform group accounting (may be empty)

        const uint32_t aS = sbase + s * STAGE_BYTES;
        const uint32_t bS = aS + A_STAGE_BYTES;

        #pragma unroll
        for (int ks = 0; ks < 4; ks++) {
            uint32_t a[4][4];
            #pragma unroll
            for (int mi = 0; mi < 4; mi++) {
                uint32_t off = (uint32_t)((a_row_l + mi * 16) * 128 + ks * 32 + a_kb_l);
                ldsm_x4(a[mi][0], a[mi][1], a[mi][2], a[mi][3], aS + sw128(off));
            }
            uint32_t b[8][2];
            #pragma unroll
            for (int np = 0; np < 4; np++) {
                uint32_t off = (uint32_t)((b_row_l + np * 16) * 128 + ks * 32 + b_kb_l);
                uint32_t r0, r1, r2, r3;
                ldsm_x4(r0, r1, r2, r3, bS + sw128(off));
                b[np * 2][0] = r0; b[np * 2][1] = r1;
                b[np * 2 + 1][0] = r2; b[np * 2 + 1][1] = r3;
            }
            #pragma unroll
            for (int mi = 0; mi < 4; mi++)
                #pragma unroll
                for (int ni = 0; ni < 8; ni++)
                    mma16816(acc[mi][ni], a[mi][0], a[mi][1], a[mi][2], a[mi][3],
                             b[ni][0], b[ni][1]);
        }
    }

    // store C
    float* gC = ((tileM < 32) ? (g_pre_i2h + (size_t)tileM * BM * NN)
                              : (g_pre_h2h + (size_t)(tileM - 32) * BM * NN))
                + (size_t)tileN * BN;
    const int mrow = warp_m * 64 + (lid >> 2);
    const int ncol = warp_n * 64 + (lid & 3) * 2;
    #pragma unroll
    for (int mi = 0; mi < 4; mi++) {
        #pragma unroll
        for (int ni = 0; ni < 8; ni++) {
            float* p0 = gC + (size_t)(mrow + mi * 16) * NN + ncol + ni * 8;
            float* p1 = gC + (size_t)(mrow + mi * 16 + 8) * NN + ncol + ni * 8;
            *reinterpret_cast<float2*>(p0) = make_float2(acc[mi][ni][0], acc[mi][ni][1]);
            *reinterpret_cast<float2*>(p1) = make_float2(acc[mi][ni][2], acc[mi][ni][3]);
        }
    }
}

// ========================= LN + gates epilogue =========================
#define EPS 1e-6f

__device__ __forceinline__ float sigm(float x) { return 1.0f / (1.0f + __expf(-x)); }
__device__ __forceinline__ float fast_tanh(float x) {
    float ax = fminf(fabsf(x), 15.0f);
    float t = __expf(2.0f * ax);
    float r = (t - 1.0f) / (t + 1.0f);
    return copysignf(r, x);
}

__device__ void block_reduce2(float& s, float& q)
{
    __shared__ __align__(16) float rs[8], rq[8];
    __shared__ float bs, bq;
    #pragma unroll
    for (int o = 16; o > 0; o >>= 1) {
        s += __shfl_down_sync(0xffffffffu, s, o);
        q += __shfl_down_sync(0xffffffffu, q, o);
    }
    const int w = threadIdx.x >> 5, l = threadIdx.x & 31;
    __syncthreads();
    if (l == 0) { rs[w] = s; rq[w] = q; }
    __syncthreads();
    if (threadIdx.x == 0) {
        float a = 0.0f, b = 0.0f;
        #pragma unroll
        for (int i = 0; i < 8; i++) { a += rs[i]; b += rq[i]; }
        bs = a; bq = b;
    }
    __syncthreads();
    s = bs; q = bq;
}

__global__ __launch_bounds__(256)
void lstm_epilogue(const float* __restrict__ c_prev,
                   const float* __restrict__ b_i2h, const float* __restrict__ b_h2h,
                   const float* __restrict__ g_i2h, const float* __restrict__ be_i2h,
                   const float* __restrict__ g_h2h, const float* __restrict__ be_h2h,
                   const float* __restrict__ g_c,   const float* __restrict__ be_c,
                   float* __restrict__ out)
{
    __shared__ __align__(16) float sh_g[NN];
    __shared__ __align__(16) float sh_h[NN];

    const int r = blockIdx.x;
    const int tid = threadIdx.x;
    const float* hi = g_pre_i2h + (size_t)r * NN;
    const float* hh = g_pre_h2h + (size_t)r * NN;

    // --- LN stats for i2h row (float4) ---
    float s = 0.0f, q = 0.0f;
    for (int j = tid * 4; j < NN; j += 1024) {
        float4 v = *reinterpret_cast<const float4*>(hi + j);
        float4 b = *reinterpret_cast<const float4*>(b_i2h + j);
        v.x += b.x; v.y += b.y; v.z += b.z; v.w += b.w;
        *reinterpret_cast<float4*>(sh_g + j) = v;
        s += v.x + v.y + v.z + v.w;
        q += v.x * v.x + v.y * v.y + v.z * v.z + v.w * v.w;
    }
    block_reduce2(s, q);
    const float m1 = s / (float)NN;
    const float v1 = (q - s * s / (float)NN) / (float)(NN - 1);
    const float inv1 = 1.0f / (sqrtf(v1) + EPS);

    // --- LN stats for h2h row ---
    s = 0.0f; q = 0.0f;
    for (int j = tid * 4; j < NN; j += 1024) {
        float4 v = *reinterpret_cast<const float4*>(hh + j);
        float4 b = *reinterpret_cast<const float4*>(b_h2h + j);
        v.x += b.x; v.y += b.y; v.z += b.z; v.w += b.w;
        *reinterpret_cast<float4*>(sh_h + j) = v;
        s += v.x + v.y + v.z + v.w;
        q += v.x * v.x + v.y * v.y + v.z * v.z + v.w * v.w;
    }
    block_reduce2(s, q);
    const float m2 = s / (float)NN;
    const float v2 = (q - s * s / (float)NN) / (float)(NN - 1);
    const float inv2 = 1.0f / (sqrtf(v2) + EPS);

    // --- normalized sum -> gates ---
    for (int j = tid * 4; j < NN; j += 1024) {
        float4 x = *reinterpret_cast<const float4*>(sh_g + j);
        float4 y = *reinterpret_cast<const float4*>(sh_h + j);
        float4 ga = *reinterpret_cast<const float4*>(g_i2h + j);
        float4 ba = *reinterpret_cast<const float4*>(be_i2h + j);
        float4 gb = *reinterpret_cast<const float4*>(g_h2h + j);
        float4 bb = *reinterpret_cast<const float4*>(be_h2h + j);
        float4 o;
        o.x = ga.x * ((x.x - m1) * inv1) + ba.x + gb.x * ((y.x - m2) * inv2) + bb.x;
        o.y = ga.y * ((x.y - m1) * inv1) + ba.y + gb.y * ((y.y - m2) * inv2) + bb.y;
        o.z = ga.z * ((x.z - m1) * inv1) + ba.z + gb.z * ((y.z - m2) * inv2) + bb.z;
        o.w = ga.w * ((x.w - m1) * inv1) + ba.w + gb.w * ((y.w - m2) * inv2) + bb.w;
        *reinterpret_cast<float4*>(sh_g + j) = o;
    }
    __syncthreads();

    // --- cell pre-activation ---
    s = 0.0f; q = 0.0f;
    for (int k = tid * 4; k < HH; k += 1024) {
        float4 ig = *reinterpret_cast<const float4*>(sh_g + k);
        float4 fg = *reinterpret_cast<const float4*>(sh_g + HH + k);
        float4 ug = *reinterpret_cast<const float4*>(sh_g + 2 * HH + k);
        float4 og = *reinterpret_cast<const float4*>(sh_g + 3 * HH + k);
        float4 cv = *reinterpret_cast<const float4*>(c_prev + (size_t)r * HH + k);
        float4 cp;
        cp.x = cv.x * sigm(fg.x + 1.0f) + fast_tanh(ug.x) * sigm(ig.x);
        cp.y = cv.y * sigm(fg.y + 1.0f) + fast_tanh(ug.y) * sigm(ig.y);
        cp.z = cv.z * sigm(fg.z + 1.0f) + fast_tanh(ug.z) * sigm(ig.z);
        cp.w = cv.w * sigm(fg.w + 1.0f) + fast_tanh(ug.w) * sigm(ig.w);
        *reinterpret_cast<float4*>(sh_h + k) = cp;
        *reinterpret_cast<float4*>(sh_h + HH + k) = og;
        s += cp.x + cp.y + cp.z + cp.w;
        q += cp.x * cp.x + cp.y * cp.y + cp.z * cp.z + cp.w * cp.w;
    }
    block_reduce2(s, q);
    const float m3 = s / (float)HH;
    const float v3 = (q - s * s / (float)HH) / (float)(HH - 1);
    const float inv3 = 1.0f / (sqrtf(v3) + EPS);

    // --- c = LN(cpre), h = sigmoid(o) * tanh(c) ---
    float* out_h = out;
    float* out_c = out + (size_t)MB * HH;
    for (int k = tid * 4; k < HH; k += 1024) {
        float4 cp = *reinterpret_cast<const float4*>(sh_h + k);
        float4 og = *reinterpret_cast<const float4*>(sh_h + HH + k);
        float4 gc = *reinterpret_cast<const float4*>(g_c + k);
        float4 bc = *reinterpret_cast<const float4*>(be_c + k);
        float4 c, h;
        c.x = gc.x * ((cp.x - m3) * inv3) + bc.x;
        c.y = gc.y * ((cp.y - m3) * inv3) + bc.y;
        c.z = gc.z * ((cp.z - m3) * inv3) + bc.z;
        c.w = gc.w * ((cp.w - m3) * inv3) + bc.w;
        h.x = sigm(og.x) * fast_tanh(c.x);
        h.y = sigm(og.y) * fast_tanh(c.y);
        h.z = sigm(og.z) * fast_tanh(c.z);
        h.w = sigm(og.w) * fast_tanh(c.w);
        *reinterpret_cast<float4*>(out_h + (size_t)r * HH + k) = h;
        *reinterpret_cast<float4*>(out_c + (size_t)r * HH + k) = c;
    }
}

// ========================= launch =========================
extern "C" void kernel_launch(void* const* d_in, const int* in_sizes, int n_in,
                              void* d_out, int out_size)
{
    const float* input  = (const float*)d_in[0];
    const float* h_prev = (const float*)d_in[1];
    const float* c_prev = (const float*)d_in[2];
    const float* w_i2h  = (const float*)d_in[3];
    const float* b_i2h  = (const float*)d_in[4];
    const float* w_h2h  = (const float*)d_in[5];
    const float* b_h2h  = (const float*)d_in[6];
    const float* g_i2h  = (const float*)d_in[7];
    const float* be_i2h = (const float*)d_in[8];
    const float* g_h2h  = (const float*)d_in[9];
    const float* be_h2h = (const float*)d_in[10];
    const float* g_c    = (const float*)d_in[11];
    const float* be_c   = (const float*)d_in[12];
    float* out = (float*)d_out;

    cudaFuncSetAttribute(gemm_bf16x3, cudaFuncAttributeMaxDynamicSharedMemorySize, GSMEM_TOTAL);

    // split-bf16 operand prep
    convert_A<<<(MTOT * KK / 2) / 256, 256>>>(input, h_prev);
    convert_B<<<dim3(NN / 32, KK / 32, 2), dim3(32, 8)>>>(w_i2h, w_h2h);

    // fused dual GEMM on HMMA (K'=3072 covers hi*hi + hi*lo + lo*hi)
    gemm_bf16x3<<<dim3(NN / BN, MTOT / BM), GTHREADS, GSMEM_TOTAL>>>();

    lstm_epilogue<<<MB, 256>>>(c_prev, b_i2h, b_h2h, g_i2h, be_i2h,
                               g_h2h, be_h2h, g_c, be_c, out);
}